// round 1
// baseline (speedup 1.0000x reference)
#include <cuda_runtime.h>
#include <math.h>

#define S   512
#define T   16384
#define D   512
#define DFF 2048
#define SEG (T / S)          // 32 frames per segment
#define MAXF (3 * SEG)       // <= 96 frames per query

// -------- scratch (allocation-free: __device__ globals) --------
__device__ float g_rctx[S * D];   // relu(ctx)
__device__ float g_t2[S * D];     // tgt + tgt2  (and reused for x + ffn)
__device__ float g_x[S * D];      // x = LN(tgt + tgt2)
__device__ float g_h[S * DFF];    // relu(x @ W1^T + b1)

// ============================================================
// Kernel 1: banded attention -> relu(ctx)
// One block per query s. 256 threads = 8 warps.
// ============================================================
__global__ __launch_bounds__(256) void attn_kernel(
    const float* __restrict__ tgt, const float* __restrict__ mem,
    const float* __restrict__ pos, const float* __restrict__ qpos,
    const int*   __restrict__ aidx)
{
    const int s   = blockIdx.x;
    const int tid = threadIdx.x;
    const int warp = tid >> 5, lane = tid & 31;

    __shared__ float q[D];
    __shared__ float sc[MAXF];
    __shared__ float denom_s;

    // q = tgt[s] + query_pos[s]
    for (int d = tid; d < D; d += 256)
        q[d] = tgt[s * D + d] + qpos[s * D + d];

    const int t0 = (s > 0) ? (s - 1) * SEG : 0;
    const int t1 = min(T, (s + 2) * SEG);
    const int nf = t1 - t0;
    __syncthreads();

    const float scale = 0.04419417382415922f;  // 1/sqrt(512)

    // scores: each warp handles frames warp, warp+8, ...
    for (int f = warp; f < nf; f += 8) {
        const int t = t0 + f;
        const float* mp = mem + (size_t)t * D;
        const float* pp = pos + (size_t)t * D;
        float acc = 0.f;
        #pragma unroll 4
        for (int d = lane; d < D; d += 32)
            acc = fmaf(q[d], mp[d] + pp[d], acc);
        #pragma unroll
        for (int o = 16; o > 0; o >>= 1)
            acc += __shfl_xor_sync(0xffffffffu, acc, o);
        if (lane == 0) {
            int a = aidx[t];
            int dlt = a - s; if (dlt < 0) dlt = -dlt;
            sc[f] = (dlt <= 1) ? acc * scale : -INFINITY;
        }
    }
    __syncthreads();

    // softmax over nf (<=96) entries, done by warp 0
    if (warp == 0) {
        float m = -INFINITY;
        for (int f = lane; f < nf; f += 32) m = fmaxf(m, sc[f]);
        #pragma unroll
        for (int o = 16; o > 0; o >>= 1)
            m = fmaxf(m, __shfl_xor_sync(0xffffffffu, m, o));
        float ssum = 0.f;
        for (int f = lane; f < nf; f += 32) {
            float e = __expf(sc[f] - m);
            sc[f] = e;
            ssum += e;
        }
        #pragma unroll
        for (int o = 16; o > 0; o >>= 1)
            ssum += __shfl_xor_sync(0xffffffffu, ssum, o);
        if (lane == 0) denom_s = ssum;
    }
    __syncthreads();
    const float inv = 1.f / denom_s;

    // ctx = sum_f p_f * mem[t0+f];  store relu(ctx)
    for (int d = tid; d < D; d += 256) {
        float acc = 0.f;
        #pragma unroll 4
        for (int f = 0; f < nf; f++)
            acc = fmaf(sc[f], mem[(size_t)(t0 + f) * D + d], acc);
        acc *= inv;
        g_rctx[s * D + d] = fmaxf(acc, 0.f);
    }
}

// ============================================================
// Tiled fp32 GEMM:  C[M,N] = A[M,K] @ W[N,K]^T + bias (+res) (opt relu)
// ============================================================
template <int BM, int BN, bool RELU>
__global__ __launch_bounds__(256) void gemm_kernel(
    const float* __restrict__ A, const float* __restrict__ W,
    const float* __restrict__ bias, const float* __restrict__ res,
    float* __restrict__ C, int M, int N, int K)
{
    constexpr int BK = 32;
    constexpr int TM = BM / 16;
    constexpr int TN = BN / 16;
    __shared__ float As[BM][BK + 1];
    __shared__ float Ws[BN][BK + 1];

    const int tid = threadIdx.x;
    const int tx = tid & 15, ty = tid >> 4;
    const int row0 = blockIdx.y * BM;
    const int col0 = blockIdx.x * BN;

    float acc[TM][TN];
    #pragma unroll
    for (int i = 0; i < TM; i++)
        #pragma unroll
        for (int j = 0; j < TN; j++) acc[i][j] = 0.f;

    for (int k0 = 0; k0 < K; k0 += BK) {
        #pragma unroll
        for (int i = tid; i < BM * BK; i += 256) {
            int r = i / BK, c = i % BK;
            As[r][c] = A[(size_t)(row0 + r) * K + k0 + c];
        }
        #pragma unroll
        for (int i = tid; i < BN * BK; i += 256) {
            int r = i / BK, c = i % BK;
            Ws[r][c] = W[(size_t)(col0 + r) * K + k0 + c];
        }
        __syncthreads();

        #pragma unroll
        for (int kk = 0; kk < BK; kk++) {
            float a[TM], b[TN];
            #pragma unroll
            for (int i = 0; i < TM; i++) a[i] = As[ty * TM + i][kk];
            #pragma unroll
            for (int j = 0; j < TN; j++) b[j] = Ws[tx * TN + j][kk];
            #pragma unroll
            for (int i = 0; i < TM; i++)
                #pragma unroll
                for (int j = 0; j < TN; j++)
                    acc[i][j] = fmaf(a[i], b[j], acc[i][j]);
        }
        __syncthreads();
    }

    #pragma unroll
    for (int i = 0; i < TM; i++) {
        const int m = row0 + ty * TM + i;
        #pragma unroll
        for (int j = 0; j < TN; j++) {
            const int n = col0 + tx * TN + j;
            float v = acc[i][j] + bias[n];
            if (RELU) v = fmaxf(v, 0.f);
            if (res)  v += res[(size_t)m * N + n];
            C[(size_t)m * N + n] = v;
        }
    }
}

// ============================================================
// LayerNorm over last dim (D=512). One block (256 thr) per row.
// ============================================================
__global__ __launch_bounds__(256) void ln_kernel(
    const float* __restrict__ in, const float* __restrict__ g,
    const float* __restrict__ be, float* __restrict__ out)
{
    const int row = blockIdx.x;
    const int tid = threadIdx.x;
    const float v0 = in[(size_t)row * D + tid];
    const float v1 = in[(size_t)row * D + tid + 256];

    __shared__ float red[8];
    __shared__ float mu_s, rstd_s;

    float s = v0 + v1;
    #pragma unroll
    for (int o = 16; o > 0; o >>= 1) s += __shfl_xor_sync(0xffffffffu, s, o);
    if ((tid & 31) == 0) red[tid >> 5] = s;
    __syncthreads();
    if (tid == 0) {
        float t = 0.f;
        #pragma unroll
        for (int i = 0; i < 8; i++) t += red[i];
        mu_s = t * (1.0f / D);
    }
    __syncthreads();
    const float mu = mu_s;
    const float d0 = v0 - mu, d1 = v1 - mu;
    float vs = d0 * d0 + d1 * d1;
    __syncthreads();  // protect red[] before reuse
    #pragma unroll
    for (int o = 16; o > 0; o >>= 1) vs += __shfl_xor_sync(0xffffffffu, vs, o);
    if ((tid & 31) == 0) red[tid >> 5] = vs;
    __syncthreads();
    if (tid == 0) {
        float t = 0.f;
        #pragma unroll
        for (int i = 0; i < 8; i++) t += red[i];
        rstd_s = rsqrtf(t * (1.0f / D) + 1e-5f);
    }
    __syncthreads();
    const float rstd = rstd_s;
    out[(size_t)row * D + tid]       = d0 * rstd * g[tid]       + be[tid];
    out[(size_t)row * D + tid + 256] = d1 * rstd * g[tid + 256] + be[tid + 256];
}

// ============================================================
extern "C" void kernel_launch(void* const* d_in, const int* in_sizes, int n_in,
                              void* d_out, int out_size)
{
    const float* tgt  = (const float*)d_in[0];
    const float* mem  = (const float*)d_in[1];
    const float* pos  = (const float*)d_in[2];
    const float* qpos = (const float*)d_in[3];
    const int*   aidx = (const int*)d_in[4];
    const float* Wt2  = (const float*)d_in[5];
    const float* bt2  = (const float*)d_in[6];
    const float* W1   = (const float*)d_in[7];
    const float* b1   = (const float*)d_in[8];
    const float* W2   = (const float*)d_in[9];
    const float* b2   = (const float*)d_in[10];
    const float* g2   = (const float*)d_in[11];
    const float* be2  = (const float*)d_in[12];
    const float* g3   = (const float*)d_in[13];
    const float* be3  = (const float*)d_in[14];
    float* out = (float*)d_out;

    float *rctx_p, *t2_p, *x_p, *h_p;
    cudaGetSymbolAddress((void**)&rctx_p, g_rctx);
    cudaGetSymbolAddress((void**)&t2_p,   g_t2);
    cudaGetSymbolAddress((void**)&x_p,    g_x);
    cudaGetSymbolAddress((void**)&h_p,    g_h);

    // 1) attention -> relu(ctx)
    attn_kernel<<<S, 256>>>(tgt, mem, pos, qpos, aidx);

    // 2) tgt2 = rctx @ Wt2^T + bt2 ; +tgt residual   [512,512,K=512]
    {
        dim3 grid(512 / 64, 512 / 32);
        gemm_kernel<32, 64, false><<<grid, 256>>>(rctx_p, Wt2, bt2, tgt, t2_p, S, D, D);
    }
    // 3) x = LN(tgt + tgt2)
    ln_kernel<<<S, 256>>>(t2_p, g2, be2, x_p);

    // 4) h = relu(x @ W1^T + b1)   [512,2048,K=512]
    {
        dim3 grid(DFF / 64, 512 / 64);
        gemm_kernel<64, 64, true><<<grid, 256>>>(x_p, W1, b1, nullptr, h_p, S, DFF, D);
    }
    // 5) y = h @ W2^T + b2 + x     [512,512,K=2048]
    {
        dim3 grid(512 / 64, 512 / 32);
        gemm_kernel<32, 64, false><<<grid, 256>>>(h_p, W2, b2, x_p, t2_p, S, D, DFF);
    }
    // 6) out = LN(x + ffn)
    ln_kernel<<<S, 256>>>(t2_p, g3, be3, out);
}

// round 2
// speedup vs baseline: 1.0099x; 1.0099x over previous
#include <cuda_runtime.h>
#include <mma.h>
#include <math.h>

using namespace nvcuda;

#define S   512
#define T   16384
#define D   512
#define DFF 2048
#define SEG (T / S)          // 32 frames per segment
#define MAXF (3 * SEG)       // <= 96 frames per query

// -------- scratch (allocation-free: __device__ globals) --------
__device__ float g_rctx[S * D];   // relu(ctx)
__device__ float g_t2[S * D];     // tgt + tgt2  (and reused for x + ffn)
__device__ float g_x[S * D];      // x = LN(tgt + tgt2)
__device__ float g_h[S * DFF];    // relu(x @ W1^T + b1)

// ============================================================
// Kernel 1: banded attention -> relu(ctx)
// One block per query s. 256 threads = 8 warps.
// ============================================================
__global__ __launch_bounds__(256) void attn_kernel(
    const float* __restrict__ tgt, const float* __restrict__ mem,
    const float* __restrict__ pos, const float* __restrict__ qpos,
    const int*   __restrict__ aidx)
{
    const int s   = blockIdx.x;
    const int tid = threadIdx.x;
    const int warp = tid >> 5, lane = tid & 31;

    __shared__ float q[D];
    __shared__ float sc[MAXF];
    __shared__ float denom_s;

    // q = tgt[s] + query_pos[s]
    for (int d = tid; d < D; d += 256)
        q[d] = tgt[s * D + d] + qpos[s * D + d];

    const int t0 = (s > 0) ? (s - 1) * SEG : 0;
    const int t1 = min(T, (s + 2) * SEG);
    const int nf = t1 - t0;
    __syncthreads();

    const float scale = 0.04419417382415922f;  // 1/sqrt(512)

    // scores: each warp handles frames warp, warp+8, ...  (float4 dots)
    for (int f = warp; f < nf; f += 8) {
        const int t = t0 + f;
        const float4* mp = (const float4*)(mem + (size_t)t * D);
        const float4* pp = (const float4*)(pos + (size_t)t * D);
        const float4* q4 = (const float4*)q;
        float acc = 0.f;
        #pragma unroll
        for (int d4 = lane; d4 < D / 4; d4 += 32) {
            float4 m = mp[d4], p = pp[d4], qq = q4[d4];
            acc = fmaf(qq.x, m.x + p.x, acc);
            acc = fmaf(qq.y, m.y + p.y, acc);
            acc = fmaf(qq.z, m.z + p.z, acc);
            acc = fmaf(qq.w, m.w + p.w, acc);
        }
        #pragma unroll
        for (int o = 16; o > 0; o >>= 1)
            acc += __shfl_xor_sync(0xffffffffu, acc, o);
        if (lane == 0) {
            int a = aidx[t];
            int dlt = a - s; if (dlt < 0) dlt = -dlt;
            sc[f] = (dlt <= 1) ? acc * scale : -INFINITY;
        }
    }
    __syncthreads();

    // softmax over nf (<=96) entries, done by warp 0
    if (warp == 0) {
        float m = -INFINITY;
        for (int f = lane; f < nf; f += 32) m = fmaxf(m, sc[f]);
        #pragma unroll
        for (int o = 16; o > 0; o >>= 1)
            m = fmaxf(m, __shfl_xor_sync(0xffffffffu, m, o));
        float ssum = 0.f;
        for (int f = lane; f < nf; f += 32) {
            float e = __expf(sc[f] - m);
            sc[f] = e;
            ssum += e;
        }
        #pragma unroll
        for (int o = 16; o > 0; o >>= 1)
            ssum += __shfl_xor_sync(0xffffffffu, ssum, o);
        if (lane == 0) denom_s = ssum;
    }
    __syncthreads();
    const float inv = 1.f / denom_s;

    // ctx = sum_f p_f * mem[t0+f];  store relu(ctx).  float2 per thread.
    {
        float2 acc2 = make_float2(0.f, 0.f);
        #pragma unroll 4
        for (int f = 0; f < nf; f++) {
            const float p = sc[f];
            float2 mv = ((const float2*)(mem + (size_t)(t0 + f) * D))[tid];
            acc2.x = fmaf(p, mv.x, acc2.x);
            acc2.y = fmaf(p, mv.y, acc2.y);
        }
        acc2.x = fmaxf(acc2.x * inv, 0.f);
        acc2.y = fmaxf(acc2.y * inv, 0.f);
        ((float2*)(g_rctx + (size_t)s * D))[tid] = acc2;
    }
}

// ============================================================
// TF32 tensor-core GEMM:  C[M,N] = A[M,K] @ W[N,K]^T + bias (+res) (opt relu)
// W is [N,K] row-major == matrix_b col_major (K x N) fragment layout.
// ============================================================
template <int BM, int BN, int WM, int WN, bool RELU>
__global__ __launch_bounds__((BM / WM) * (BN / WN) * 32) void gemm_tc(
    const float* __restrict__ A, const float* __restrict__ W,
    const float* __restrict__ bias, const float* __restrict__ res,
    float* __restrict__ C, int M, int N, int K)
{
    constexpr int BK = 32;
    constexpr int WARPS_M = BM / WM;
    constexpr int WARPS_N = BN / WN;
    constexpr int THREADS = WARPS_M * WARPS_N * 32;
    constexpr int TM = WM / 16;
    constexpr int TN = WN / 16;
    constexpr int LDS_A = BK + 4;
    constexpr int LDS_C = BN + 4;

    __shared__ float As[BM][LDS_A];
    __shared__ float Bs[BN][LDS_A];
    __shared__ float Cs[BM][LDS_C];

    const int tid  = threadIdx.x;
    const int warp = tid >> 5;
    const int wm = warp / WARPS_N, wn = warp % WARPS_N;
    const int row0 = blockIdx.y * BM;
    const int col0 = blockIdx.x * BN;

    wmma::fragment<wmma::accumulator, 16, 16, 8, float> acc[TM][TN];
    #pragma unroll
    for (int i = 0; i < TM; i++)
        #pragma unroll
        for (int j = 0; j < TN; j++)
            wmma::fill_fragment(acc[i][j], 0.f);

    for (int k0 = 0; k0 < K; k0 += BK) {
        // load A tile (vectorized float4; row stride LDS_A*4 bytes = 144, 16B aligned)
        #pragma unroll
        for (int i = tid; i < BM * (BK / 4); i += THREADS) {
            int r = i / (BK / 4), c = (i % (BK / 4)) * 4;
            *(float4*)&As[r][c] = *(const float4*)&A[(size_t)(row0 + r) * K + k0 + c];
        }
        #pragma unroll
        for (int i = tid; i < BN * (BK / 4); i += THREADS) {
            int r = i / (BK / 4), c = (i % (BK / 4)) * 4;
            *(float4*)&Bs[r][c] = *(const float4*)&W[(size_t)(col0 + r) * K + k0 + c];
        }
        __syncthreads();

        #pragma unroll
        for (int kk = 0; kk < BK; kk += 8) {
            wmma::fragment<wmma::matrix_a, 16, 16, 8, wmma::precision::tf32, wmma::row_major> fa[TM];
            wmma::fragment<wmma::matrix_b, 16, 16, 8, wmma::precision::tf32, wmma::col_major> fb[TN];
            #pragma unroll
            for (int i = 0; i < TM; i++) {
                wmma::load_matrix_sync(fa[i], &As[wm * WM + i * 16][kk], LDS_A);
                #pragma unroll
                for (int e = 0; e < fa[i].num_elements; e++)
                    fa[i].x[e] = wmma::__float_to_tf32(fa[i].x[e]);
            }
            #pragma unroll
            for (int j = 0; j < TN; j++) {
                wmma::load_matrix_sync(fb[j], &Bs[wn * WN + j * 16][kk], LDS_A);
                #pragma unroll
                for (int e = 0; e < fb[j].num_elements; e++)
                    fb[j].x[e] = wmma::__float_to_tf32(fb[j].x[e]);
            }
            #pragma unroll
            for (int i = 0; i < TM; i++)
                #pragma unroll
                for (int j = 0; j < TN; j++)
                    wmma::mma_sync(acc[i][j], fa[i], fb[j], acc[i][j]);
        }
        __syncthreads();
    }

    // epilogue via shared
    #pragma unroll
    for (int i = 0; i < TM; i++)
        #pragma unroll
        for (int j = 0; j < TN; j++)
            wmma::store_matrix_sync(&Cs[wm * WM + i * 16][wn * WN + j * 16],
                                    acc[i][j], LDS_C, wmma::mem_row_major);
    __syncthreads();

    #pragma unroll
    for (int i = tid; i < BM * BN; i += THREADS) {
        int r = i / BN, c = i % BN;
        float v = Cs[r][c] + bias[col0 + c];
        if (RELU) v = fmaxf(v, 0.f);
        if (res)  v += res[(size_t)(row0 + r) * N + col0 + c];
        C[(size_t)(row0 + r) * N + col0 + c] = v;
    }
}

// ============================================================
// LayerNorm over last dim (D=512). One block (256 thr) per row.
// ============================================================
__global__ __launch_bounds__(256) void ln_kernel(
    const float* __restrict__ in, const float* __restrict__ g,
    const float* __restrict__ be, float* __restrict__ out)
{
    const int row = blockIdx.x;
    const int tid = threadIdx.x;
    const float v0 = in[(size_t)row * D + tid];
    const float v1 = in[(size_t)row * D + tid + 256];

    __shared__ float red[8];
    __shared__ float mu_s, rstd_s;

    float s = v0 + v1;
    #pragma unroll
    for (int o = 16; o > 0; o >>= 1) s += __shfl_xor_sync(0xffffffffu, s, o);
    if ((tid & 31) == 0) red[tid >> 5] = s;
    __syncthreads();
    if (tid == 0) {
        float t = 0.f;
        #pragma unroll
        for (int i = 0; i < 8; i++) t += red[i];
        mu_s = t * (1.0f / D);
    }
    __syncthreads();
    const float mu = mu_s;
    const float d0 = v0 - mu, d1 = v1 - mu;
    float vs = d0 * d0 + d1 * d1;
    __syncthreads();  // protect red[] before reuse
    #pragma unroll
    for (int o = 16; o > 0; o >>= 1) vs += __shfl_xor_sync(0xffffffffu, vs, o);
    if ((tid & 31) == 0) red[tid >> 5] = vs;
    __syncthreads();
    if (tid == 0) {
        float t = 0.f;
        #pragma unroll
        for (int i = 0; i < 8; i++) t += red[i];
        rstd_s = rsqrtf(t * (1.0f / D) + 1e-5f);
    }
    __syncthreads();
    const float rstd = rstd_s;
    out[(size_t)row * D + tid]       = d0 * rstd * g[tid]       + be[tid];
    out[(size_t)row * D + tid + 256] = d1 * rstd * g[tid + 256] + be[tid + 256];
}

// ============================================================
extern "C" void kernel_launch(void* const* d_in, const int* in_sizes, int n_in,
                              void* d_out, int out_size)
{
    const float* tgt  = (const float*)d_in[0];
    const float* mem  = (const float*)d_in[1];
    const float* pos  = (const float*)d_in[2];
    const float* qpos = (const float*)d_in[3];
    const int*   aidx = (const int*)d_in[4];
    const float* Wt2  = (const float*)d_in[5];
    const float* bt2  = (const float*)d_in[6];
    const float* W1   = (const float*)d_in[7];
    const float* b1   = (const float*)d_in[8];
    const float* W2   = (const float*)d_in[9];
    const float* b2   = (const float*)d_in[10];
    const float* g2   = (const float*)d_in[11];
    const float* be2  = (const float*)d_in[12];
    const float* g3   = (const float*)d_in[13];
    const float* be3  = (const float*)d_in[14];
    float* out = (float*)d_out;

    float *rctx_p, *t2_p, *x_p, *h_p;
    cudaGetSymbolAddress((void**)&rctx_p, g_rctx);
    cudaGetSymbolAddress((void**)&t2_p,   g_t2);
    cudaGetSymbolAddress((void**)&x_p,    g_x);
    cudaGetSymbolAddress((void**)&h_p,    g_h);

    // 1) attention -> relu(ctx)
    attn_kernel<<<S, 256>>>(tgt, mem, pos, qpos, aidx);

    // 2) tgt2 = rctx @ Wt2^T + bt2 ; +tgt residual   [M=512,N=512,K=512]
    {
        dim3 grid(D / 32, S / 64);
        gemm_tc<64, 32, 32, 16, false><<<grid, 128>>>(rctx_p, Wt2, bt2, tgt, t2_p, S, D, D);
    }
    // 3) x = LN(tgt + tgt2)
    ln_kernel<<<S, 256>>>(t2_p, g2, be2, x_p);

    // 4) h = relu(x @ W1^T + b1)   [M=512,N=2048,K=512]
    {
        dim3 grid(DFF / 64, S / 64);
        gemm_tc<64, 64, 32, 32, true><<<grid, 128>>>(x_p, W1, b1, nullptr, h_p, S, DFF, D);
    }
    // 5) y = h @ W2^T + b2 + x     [M=512,N=512,K=2048]
    {
        dim3 grid(D / 32, S / 64);
        gemm_tc<64, 32, 32, 16, false><<<grid, 128>>>(h_p, W2, b2, x_p, t2_p, S, D, DFF);
    }
    // 6) out = LN(x + ffn)
    ln_kernel<<<S, 256>>>(t2_p, g3, be3, out);
}

// round 6
// speedup vs baseline: 1.9007x; 1.8820x over previous
#include <cuda_runtime.h>
#include <cstdint>
#include <mma.h>
#include <math.h>

using namespace nvcuda;

#define S   512
#define T   16384
#define D   512
#define DFF 2048
#define SEG (T / S)          // 32 frames per segment
#define G   4                // queries per attention block

// -------- scratch (allocation-free: __device__ globals) --------
__device__ float g_rctx[S * D];     // relu(ctx)
__device__ float g_x[S * D];        // x = LN(tgt + tgt2)
__device__ float g_h[S * DFF];      // relu(x @ W1^T + b1)
__device__ float g_part[2 * S * D]; // split-K partial sums

// ============================================================
// cp.async helpers
// ============================================================
__device__ __forceinline__ void cp_async16(void* sm, const void* gm) {
    unsigned int a = (unsigned int)__cvta_generic_to_shared(sm);
    asm volatile("cp.async.cg.shared.global [%0], [%1], 16;" :: "r"(a), "l"(gm) : "memory");
}
__device__ __forceinline__ void cp_commit() {
    asm volatile("cp.async.commit_group;" ::: "memory");
}
__device__ __forceinline__ void cp_wait1() {
    asm volatile("cp.async.wait_group 1;" ::: "memory");
}

// ============================================================
// Kernel 1: banded attention -> relu(ctx). G=4 queries / block.
// 512 threads = 16 warps. Frames union: segments [q0-1, q0+4].
// ============================================================
__global__ __launch_bounds__(512) void attn_kernel(
    const float* __restrict__ tgt, const float* __restrict__ mem,
    const float* __restrict__ pos, const float* __restrict__ qpos,
    const int*   __restrict__ aidx)
{
    const int blk  = blockIdx.x;
    const int tid  = threadIdx.x;
    const int warp = tid >> 5, lane = tid & 31;
    const int q0   = blk * G;

    const int t0 = max(0, q0 - 1) * SEG;
    const int t1 = min(S, q0 + G + 1) * SEG;
    const int nf = t1 - t0;                      // <= 192

    __shared__ float4 qs[G][D / 4];
    __shared__ float  sp[G][(G + 2) * SEG];
    __shared__ float  invd[G];

    // q = tgt + query_pos for 4 queries
    for (int i = tid; i < G * (D / 4); i += 512) {
        int qi = i / (D / 4), d4 = i % (D / 4);
        float4 tv = ((const float4*)tgt)[(size_t)(q0 + qi) * (D / 4) + d4];
        float4 pv = ((const float4*)qpos)[(size_t)(q0 + qi) * (D / 4) + d4];
        qs[qi][d4] = make_float4(tv.x + pv.x, tv.y + pv.y, tv.z + pv.z, tv.w + pv.w);
    }
    __syncthreads();

    const float scale = 0.04419417382415922f;  // 1/sqrt(512)

    // scores: each warp takes frames warp, warp+16, ...; 4 dots per frame
    for (int f = warp; f < nf; f += 16) {
        const int t = t0 + f;
        const float4* mp = (const float4*)mem + (size_t)t * (D / 4);
        const float4* pp = (const float4*)pos + (size_t)t * (D / 4);
        float a0 = 0.f, a1 = 0.f, a2 = 0.f, a3 = 0.f;
        #pragma unroll
        for (int i = 0; i < 4; i++) {
            const int d4 = lane + 32 * i;
            float4 m = mp[d4], p = pp[d4];
            float4 k = make_float4(m.x + p.x, m.y + p.y, m.z + p.z, m.w + p.w);
            float4 qa = qs[0][d4], qb = qs[1][d4], qc = qs[2][d4], qd = qs[3][d4];
            a0 = fmaf(k.x, qa.x, fmaf(k.y, qa.y, fmaf(k.z, qa.z, fmaf(k.w, qa.w, a0))));
            a1 = fmaf(k.x, qb.x, fmaf(k.y, qb.y, fmaf(k.z, qb.z, fmaf(k.w, qb.w, a1))));
            a2 = fmaf(k.x, qc.x, fmaf(k.y, qc.y, fmaf(k.z, qc.z, fmaf(k.w, qc.w, a2))));
            a3 = fmaf(k.x, qd.x, fmaf(k.y, qd.y, fmaf(k.z, qd.z, fmaf(k.w, qd.w, a3))));
        }
        #pragma unroll
        for (int o = 16; o > 0; o >>= 1) {
            a0 += __shfl_xor_sync(0xffffffffu, a0, o);
            a1 += __shfl_xor_sync(0xffffffffu, a1, o);
            a2 += __shfl_xor_sync(0xffffffffu, a2, o);
            a3 += __shfl_xor_sync(0xffffffffu, a3, o);
        }
        if (lane == 0) {
            const int a = aidx[t];
            int d0 = a - q0;     if (d0 < 0) d0 = -d0;
            int d1 = a - q0 - 1; if (d1 < 0) d1 = -d1;
            int d2 = a - q0 - 2; if (d2 < 0) d2 = -d2;
            int d3 = a - q0 - 3; if (d3 < 0) d3 = -d3;
            sp[0][f] = (d0 <= 1) ? a0 * scale : -INFINITY;
            sp[1][f] = (d1 <= 1) ? a1 * scale : -INFINITY;
            sp[2][f] = (d2 <= 1) ? a2 * scale : -INFINITY;
            sp[3][f] = (d3 <= 1) ? a3 * scale : -INFINITY;
        }
    }
    __syncthreads();

    // softmax: warp qi handles query qi
    if (warp < G) {
        const int qi = warp;
        float m = -INFINITY;
        for (int f = lane; f < nf; f += 32) m = fmaxf(m, sp[qi][f]);
        #pragma unroll
        for (int o = 16; o > 0; o >>= 1)
            m = fmaxf(m, __shfl_xor_sync(0xffffffffu, m, o));
        float ssum = 0.f;
        for (int f = lane; f < nf; f += 32) {
            float e = __expf(sp[qi][f] - m);
            sp[qi][f] = e;
            ssum += e;
        }
        #pragma unroll
        for (int o = 16; o > 0; o >>= 1)
            ssum += __shfl_xor_sync(0xffffffffu, ssum, o);
        if (lane == 0) invd[qi] = 1.f / ssum;
    }
    __syncthreads();

    // ctx: thread -> (query, float4 chunk). 4 x 128 threads.
    {
        const int qi = tid >> 7;
        const int dc = tid & 127;
        const int s  = q0 + qi;
        const int fb = max(0, s - 1) * SEG - t0;
        const int fe = min(S, s + 2) * SEG - t0;
        const float4* m4 = (const float4*)mem;
        float4 acc = make_float4(0.f, 0.f, 0.f, 0.f);
        #pragma unroll 4
        for (int f = fb; f < fe; f++) {
            const float p = sp[qi][f];
            float4 mv = m4[(size_t)(t0 + f) * (D / 4) + dc];
            acc.x = fmaf(p, mv.x, acc.x);
            acc.y = fmaf(p, mv.y, acc.y);
            acc.z = fmaf(p, mv.z, acc.z);
            acc.w = fmaf(p, mv.w, acc.w);
        }
        const float iv = invd[qi];
        acc.x = fmaxf(acc.x * iv, 0.f);
        acc.y = fmaxf(acc.y * iv, 0.f);
        acc.z = fmaxf(acc.z * iv, 0.f);
        acc.w = fmaxf(acc.w * iv, 0.f);
        ((float4*)g_rctx)[(size_t)s * (D / 4) + dc] = acc;
    }
}

// ============================================================
// TF32 tensor-core GEMM, double-buffered cp.async pipeline.
// C[M,N] (+= over grid.z halves of K) = A[M,K] @ W[N,K]^T
// KSPLIT>1: writes raw partials to C + z*M*N (bias applied later).
// BIASRELU: v = relu(acc + bias) (FFN-up).
// ============================================================
template <int BM, int BN, int WM, int WN, int KSPLIT, bool BIASRELU>
__global__ __launch_bounds__(256) void gemm_tc(
    const float* __restrict__ A, const float* __restrict__ W,
    const float* __restrict__ bias, float* __restrict__ C,
    int M, int N, int K)
{
    constexpr int BK = 32;
    constexpr int WARPS_M = BM / WM;
    constexpr int WARPS_N = BN / WN;
    static_assert(WARPS_M * WARPS_N == 8, "need 8 warps");
    constexpr int TM = WM / 16;
    constexpr int TN = WN / 16;
    constexpr int LDA = BK + 4;
    constexpr int LDC = BN + 4;

    __shared__ union SmemU {
        struct { float A[2][BM][LDA]; float B[2][BN][LDA]; } s;
        float Cs[BM][LDC];
    } sm;

    const int tid  = threadIdx.x;
    const int warp = tid >> 5;
    const int wm = warp / WARPS_N, wn = warp % WARPS_N;
    const int col0 = blockIdx.x * BN;
    const int row0 = blockIdx.y * BM;
    const int Kloc = K / KSPLIT;
    const int kbase = blockIdx.z * Kloc;
    float* Cout = C + (size_t)blockIdx.z * M * N;

    wmma::fragment<wmma::accumulator, 16, 16, 8, float> acc[TM][TN];
    #pragma unroll
    for (int i = 0; i < TM; i++)
        #pragma unroll
        for (int j = 0; j < TN; j++)
            wmma::fill_fragment(acc[i][j], 0.f);

    const int NIT = Kloc / BK;

    auto load_tile = [&](int it, int st) {
        const int k0 = kbase + it * BK;
        #pragma unroll
        for (int i = tid; i < BM * (BK / 4); i += 256) {
            int r = i / (BK / 4), c = (i % (BK / 4)) * 4;
            cp_async16(&sm.s.A[st][r][c], &A[(size_t)(row0 + r) * K + k0 + c]);
        }
        #pragma unroll
        for (int i = tid; i < BN * (BK / 4); i += 256) {
            int r = i / (BK / 4), c = (i % (BK / 4)) * 4;
            cp_async16(&sm.s.B[st][r][c], &W[(size_t)(col0 + r) * K + k0 + c]);
        }
    };

    load_tile(0, 0);
    cp_commit();

    for (int it = 0; it < NIT; it++) {
        if (it + 1 < NIT) load_tile(it + 1, (it + 1) & 1);
        cp_commit();                    // (possibly empty) group keeps wait<1> exact
        cp_wait1();
        __syncthreads();

        const int st = it & 1;
        #pragma unroll
        for (int kk = 0; kk < BK; kk += 8) {
            wmma::fragment<wmma::matrix_a, 16, 16, 8, wmma::precision::tf32, wmma::row_major> fa[TM];
            wmma::fragment<wmma::matrix_b, 16, 16, 8, wmma::precision::tf32, wmma::col_major> fb[TN];
            #pragma unroll
            for (int i = 0; i < TM; i++)
                wmma::load_matrix_sync(fa[i], &sm.s.A[st][wm * WM + i * 16][kk], LDA);
            #pragma unroll
            for (int j = 0; j < TN; j++)
                wmma::load_matrix_sync(fb[j], &sm.s.B[st][wn * WN + j * 16][kk], LDA);
            #pragma unroll
            for (int i = 0; i < TM; i++)
                #pragma unroll
                for (int j = 0; j < TN; j++)
                    wmma::mma_sync(acc[i][j], fa[i], fb[j], acc[i][j]);
        }
        __syncthreads();
    }

    // epilogue: frags -> smem (aliased over stage buffers) -> global
    #pragma unroll
    for (int i = 0; i < TM; i++)
        #pragma unroll
        for (int j = 0; j < TN; j++)
            wmma::store_matrix_sync(&sm.Cs[wm * WM + i * 16][wn * WN + j * 16],
                                    acc[i][j], LDC, wmma::mem_row_major);
    __syncthreads();

    #pragma unroll
    for (int i = tid; i < BM * (BN / 4); i += 256) {
        int r = i / (BN / 4), c = (i % (BN / 4)) * 4;
        float4 v = *(float4*)&sm.Cs[r][c];
        if (BIASRELU) {
            float4 b4 = *(const float4*)&bias[col0 + c];
            v.x = fmaxf(v.x + b4.x, 0.f);
            v.y = fmaxf(v.y + b4.y, 0.f);
            v.z = fmaxf(v.z + b4.z, 0.f);
            v.w = fmaxf(v.w + b4.w, 0.f);
        }
        *(float4*)&Cout[(size_t)(row0 + r) * N + col0 + c] = v;
    }
}

// ============================================================
// LayerNorm with fused split-K combine:
// v = p0 + p1 + res + bias[n]; out = LN(v) * g + be
// ============================================================
__global__ __launch_bounds__(256) void ln_kernel(
    const float* __restrict__ p0, const float* __restrict__ p1,
    const float* __restrict__ bias, const float* __restrict__ res,
    const float* __restrict__ g, const float* __restrict__ be,
    float* __restrict__ out)
{
    const int row = blockIdx.x;
    const int tid = threadIdx.x;
    const size_t i0 = (size_t)row * D + tid;
    const size_t i1 = i0 + 256;
    const float v0 = p0[i0] + p1[i0] + res[i0] + bias[tid];
    const float v1 = p0[i1] + p1[i1] + res[i1] + bias[tid + 256];

    __shared__ float red[8];
    __shared__ float mu_s, rstd_s;

    float s = v0 + v1;
    #pragma unroll
    for (int o = 16; o > 0; o >>= 1) s += __shfl_xor_sync(0xffffffffu, s, o);
    if ((tid & 31) == 0) red[tid >> 5] = s;
    __syncthreads();
    if (tid == 0) {
        float t = 0.f;
        #pragma unroll
        for (int i = 0; i < 8; i++) t += red[i];
        mu_s = t * (1.0f / D);
    }
    __syncthreads();
    const float mu = mu_s;
    const float d0 = v0 - mu, d1 = v1 - mu;
    float vs = d0 * d0 + d1 * d1;
    __syncthreads();
    #pragma unroll
    for (int o = 16; o > 0; o >>= 1) vs += __shfl_xor_sync(0xffffffffu, vs, o);
    if ((tid & 31) == 0) red[tid >> 5] = vs;
    __syncthreads();
    if (tid == 0) {
        float t = 0.f;
        #pragma unroll
        for (int i = 0; i < 8; i++) t += red[i];
        rstd_s = rsqrtf(t * (1.0f / D) + 1e-5f);
    }
    __syncthreads();
    const float rstd = rstd_s;
    out[i0] = d0 * rstd * g[tid] + be[tid];
    out[i1] = d1 * rstd * g[tid + 256] + be[tid + 256];
}

// ============================================================
extern "C" void kernel_launch(void* const* d_in, const int* in_sizes, int n_in,
                              void* d_out, int out_size)
{
    const float* tgt  = (const float*)d_in[0];
    const float* mem  = (const float*)d_in[1];
    const float* pos  = (const float*)d_in[2];
    const float* qpos = (const float*)d_in[3];
    const int*   aidx = (const int*)d_in[4];
    const float* Wt2  = (const float*)d_in[5];
    const float* bt2  = (const float*)d_in[6];
    const float* W1   = (const float*)d_in[7];
    const float* b1   = (const float*)d_in[8];
    const float* W2   = (const float*)d_in[9];
    const float* b2   = (const float*)d_in[10];
    const float* g2   = (const float*)d_in[11];
    const float* be2  = (const float*)d_in[12];
    const float* g3   = (const float*)d_in[13];
    const float* be3  = (const float*)d_in[14];
    float* out = (float*)d_out;

    float *rctx_p, *x_p, *h_p, *part_p;
    cudaGetSymbolAddress((void**)&rctx_p, g_rctx);
    cudaGetSymbolAddress((void**)&x_p,    g_x);
    cudaGetSymbolAddress((void**)&h_p,    g_h);
    cudaGetSymbolAddress((void**)&part_p, g_part);

    // 1) attention -> relu(ctx)
    attn_kernel<<<S / G, 512>>>(tgt, mem, pos, qpos, aidx);

    // 2) tgt2 partials = rctx @ Wt2^T   [M=512,N=512,K=512], split-K=2
    {
        dim3 grid(D / 32, S / 64, 2);
        gemm_tc<64, 32, 16, 16, 2, false><<<grid, 256>>>(rctx_p, Wt2, nullptr, part_p, S, D, D);
    }
    // 3) x = LN(tgt + p0 + p1 + bt2)
    ln_kernel<<<S, 256>>>(part_p, part_p + S * D, bt2, tgt, g2, be2, x_p);

    // 4) h = relu(x @ W1^T + b1)   [M=512,N=2048,K=512]
    {
        dim3 grid(DFF / 64, S / 64, 1);
        gemm_tc<64, 64, 32, 16, 1, true><<<grid, 256>>>(x_p, W1, b1, h_p, S, DFF, D);
    }
    // 5) ffn partials = h @ W2^T   [M=512,N=512,K=2048], split-K=2
    {
        dim3 grid(D / 32, S / 64, 2);
        gemm_tc<64, 32, 16, 16, 2, false><<<grid, 256>>>(h_p, W2, nullptr, part_p, S, D, DFF);
    }
    // 6) out = LN(x + p0 + p1 + b2)
    ln_kernel<<<S, 256>>>(part_p, part_p + S * D, b2, x_p, g3, be3, out);
}

// round 7
// speedup vs baseline: 2.0329x; 1.0695x over previous
#include <cuda_runtime.h>
#include <cstdint>
#include <mma.h>
#include <math.h>

using namespace nvcuda;

#define S   512
#define T   16384
#define D   512
#define DFF 2048
#define SEG (T / S)          // 32 frames per segment
#define G   4                // queries per attention block

// -------- scratch (allocation-free: __device__ globals) --------
__device__ float g_rctx[S * D];     // relu(ctx)
__device__ float g_x[S * D];        // x = LN(tgt + tgt2)
__device__ float g_h[S * DFF];      // relu(x @ W1^T + b1)
__device__ float g_part[4 * S * D]; // split-K partial sums (up to 4)

// ============================================================
// cp.async helpers
// ============================================================
__device__ __forceinline__ void cp_async16(void* sm, const void* gm) {
    unsigned int a = (unsigned int)__cvta_generic_to_shared(sm);
    asm volatile("cp.async.cg.shared.global [%0], [%1], 16;" :: "r"(a), "l"(gm) : "memory");
}
__device__ __forceinline__ void cp_commit() {
    asm volatile("cp.async.commit_group;" ::: "memory");
}
__device__ __forceinline__ void cp_wait1() {
    asm volatile("cp.async.wait_group 1;" ::: "memory");
}

// ============================================================
// Kernel 1: banded attention -> relu(ctx). G=4 queries / block.
// 512 threads = 16 warps. Score loop: 2 frames in flight per warp.
// ============================================================
__global__ __launch_bounds__(512) void attn_kernel(
    const float* __restrict__ tgt, const float* __restrict__ mem,
    const float* __restrict__ pos, const float* __restrict__ qpos,
    const int*   __restrict__ aidx)
{
    const int blk  = blockIdx.x;
    const int tid  = threadIdx.x;
    const int warp = tid >> 5, lane = tid & 31;
    const int q0   = blk * G;

    const int t0 = max(0, q0 - 1) * SEG;
    const int t1 = min(S, q0 + G + 1) * SEG;
    const int nf = t1 - t0;                      // 160 or 192

    __shared__ float4 qs[G][D / 4];
    __shared__ float  sp[G][(G + 2) * SEG];
    __shared__ float  invd[G];

    for (int i = tid; i < G * (D / 4); i += 512) {
        int qi = i / (D / 4), d4 = i % (D / 4);
        float4 tv = ((const float4*)tgt)[(size_t)(q0 + qi) * (D / 4) + d4];
        float4 pv = ((const float4*)qpos)[(size_t)(q0 + qi) * (D / 4) + d4];
        qs[qi][d4] = make_float4(tv.x + pv.x, tv.y + pv.y, tv.z + pv.z, tv.w + pv.w);
    }
    __syncthreads();

    const float scale = 0.04419417382415922f;  // 1/sqrt(512)

    // scores: warp handles frame pair (base, base+16) per iteration
    for (int base = warp; base < nf; base += 32) {
        const int fA = base;
        const int fB = base + 16;
        const bool hasB = fB < nf;
        const int tA = t0 + fA;
        const int tB = t0 + (hasB ? fB : fA);
        const float4* mA = (const float4*)mem + (size_t)tA * (D / 4);
        const float4* pA = (const float4*)pos + (size_t)tA * (D / 4);
        const float4* mB = (const float4*)mem + (size_t)tB * (D / 4);
        const float4* pB = (const float4*)pos + (size_t)tB * (D / 4);

        float aA0 = 0.f, aA1 = 0.f, aA2 = 0.f, aA3 = 0.f;
        float aB0 = 0.f, aB1 = 0.f, aB2 = 0.f, aB3 = 0.f;
        #pragma unroll
        for (int i = 0; i < 4; i++) {
            const int d4 = lane + 32 * i;
            float4 ma = mA[d4], pa = pA[d4];
            float4 mb = mB[d4], pb = pB[d4];
            float4 kA = make_float4(ma.x + pa.x, ma.y + pa.y, ma.z + pa.z, ma.w + pa.w);
            float4 kB = make_float4(mb.x + pb.x, mb.y + pb.y, mb.z + pb.z, mb.w + pb.w);
            float4 qa = qs[0][d4], qb = qs[1][d4], qc = qs[2][d4], qd = qs[3][d4];
            aA0 = fmaf(kA.x, qa.x, fmaf(kA.y, qa.y, fmaf(kA.z, qa.z, fmaf(kA.w, qa.w, aA0))));
            aA1 = fmaf(kA.x, qb.x, fmaf(kA.y, qb.y, fmaf(kA.z, qb.z, fmaf(kA.w, qb.w, aA1))));
            aA2 = fmaf(kA.x, qc.x, fmaf(kA.y, qc.y, fmaf(kA.z, qc.z, fmaf(kA.w, qc.w, aA2))));
            aA3 = fmaf(kA.x, qd.x, fmaf(kA.y, qd.y, fmaf(kA.z, qd.z, fmaf(kA.w, qd.w, aA3))));
            aB0 = fmaf(kB.x, qa.x, fmaf(kB.y, qa.y, fmaf(kB.z, qa.z, fmaf(kB.w, qa.w, aB0))));
            aB1 = fmaf(kB.x, qb.x, fmaf(kB.y, qb.y, fmaf(kB.z, qb.z, fmaf(kB.w, qb.w, aB1))));
            aB2 = fmaf(kB.x, qc.x, fmaf(kB.y, qc.y, fmaf(kB.z, qc.z, fmaf(kB.w, qc.w, aB2))));
            aB3 = fmaf(kB.x, qd.x, fmaf(kB.y, qd.y, fmaf(kB.z, qd.z, fmaf(kB.w, qd.w, aB3))));
        }
        #pragma unroll
        for (int o = 16; o > 0; o >>= 1) {
            aA0 += __shfl_xor_sync(0xffffffffu, aA0, o);
            aA1 += __shfl_xor_sync(0xffffffffu, aA1, o);
            aA2 += __shfl_xor_sync(0xffffffffu, aA2, o);
            aA3 += __shfl_xor_sync(0xffffffffu, aA3, o);
            aB0 += __shfl_xor_sync(0xffffffffu, aB0, o);
            aB1 += __shfl_xor_sync(0xffffffffu, aB1, o);
            aB2 += __shfl_xor_sync(0xffffffffu, aB2, o);
            aB3 += __shfl_xor_sync(0xffffffffu, aB3, o);
        }
        if (lane == 0) {
            {
                const int a = aidx[tA];
                int d0 = a - q0;     if (d0 < 0) d0 = -d0;
                int d1 = a - q0 - 1; if (d1 < 0) d1 = -d1;
                int d2 = a - q0 - 2; if (d2 < 0) d2 = -d2;
                int d3 = a - q0 - 3; if (d3 < 0) d3 = -d3;
                sp[0][fA] = (d0 <= 1) ? aA0 * scale : -INFINITY;
                sp[1][fA] = (d1 <= 1) ? aA1 * scale : -INFINITY;
                sp[2][fA] = (d2 <= 1) ? aA2 * scale : -INFINITY;
                sp[3][fA] = (d3 <= 1) ? aA3 * scale : -INFINITY;
            }
            if (hasB) {
                const int a = aidx[tB];
                int d0 = a - q0;     if (d0 < 0) d0 = -d0;
                int d1 = a - q0 - 1; if (d1 < 0) d1 = -d1;
                int d2 = a - q0 - 2; if (d2 < 0) d2 = -d2;
                int d3 = a - q0 - 3; if (d3 < 0) d3 = -d3;
                sp[0][fB] = (d0 <= 1) ? aB0 * scale : -INFINITY;
                sp[1][fB] = (d1 <= 1) ? aB1 * scale : -INFINITY;
                sp[2][fB] = (d2 <= 1) ? aB2 * scale : -INFINITY;
                sp[3][fB] = (d3 <= 1) ? aB3 * scale : -INFINITY;
            }
        }
    }
    __syncthreads();

    // softmax: warp qi handles query qi
    if (warp < G) {
        const int qi = warp;
        float m = -INFINITY;
        for (int f = lane; f < nf; f += 32) m = fmaxf(m, sp[qi][f]);
        #pragma unroll
        for (int o = 16; o > 0; o >>= 1)
            m = fmaxf(m, __shfl_xor_sync(0xffffffffu, m, o));
        float ssum = 0.f;
        for (int f = lane; f < nf; f += 32) {
            float e = __expf(sp[qi][f] - m);
            sp[qi][f] = e;
            ssum += e;
        }
        #pragma unroll
        for (int o = 16; o > 0; o >>= 1)
            ssum += __shfl_xor_sync(0xffffffffu, ssum, o);
        if (lane == 0) invd[qi] = 1.f / ssum;
    }
    __syncthreads();

    // ctx: thread -> (query, float4 chunk)
    {
        const int qi = tid >> 7;
        const int dc = tid & 127;
        const int s  = q0 + qi;
        const int fb = max(0, s - 1) * SEG - t0;
        const int fe = min(S, s + 2) * SEG - t0;
        const float4* m4 = (const float4*)mem;
        float4 acc = make_float4(0.f, 0.f, 0.f, 0.f);
        #pragma unroll 4
        for (int f = fb; f < fe; f++) {
            const float p = sp[qi][f];
            float4 mv = m4[(size_t)(t0 + f) * (D / 4) + dc];
            acc.x = fmaf(p, mv.x, acc.x);
            acc.y = fmaf(p, mv.y, acc.y);
            acc.z = fmaf(p, mv.z, acc.z);
            acc.w = fmaf(p, mv.w, acc.w);
        }
        const float iv = invd[qi];
        acc.x = fmaxf(acc.x * iv, 0.f);
        acc.y = fmaxf(acc.y * iv, 0.f);
        acc.z = fmaxf(acc.z * iv, 0.f);
        acc.w = fmaxf(acc.w * iv, 0.f);
        ((float4*)g_rctx)[(size_t)s * (D / 4) + dc] = acc;
    }
}

// ============================================================
// TF32 tensor-core GEMM, double-buffered cp.async pipeline.
// BM=64, BN=128, warp tile 32x32 (TM=2,TN=2), 8 warps.
// KSPLIT>1: raw partials to C + z*M*N (bias applied in LN).
// ============================================================
template <int KSPLIT, bool BIASRELU>
__global__ __launch_bounds__(256) void gemm_tc(
    const float* __restrict__ A, const float* __restrict__ W,
    const float* __restrict__ bias, float* __restrict__ C,
    int M, int N, int K)
{
    constexpr int BM = 64, BN = 128, BK = 32;
    constexpr int WM = 32, WN = 32;
    constexpr int WARPS_N = BN / WN;           // 4
    constexpr int TM = WM / 16, TN = WN / 16;  // 2, 2
    constexpr int LDA = BK + 4;
    constexpr int LDC = BN + 4;

    __shared__ union SmemU {
        struct { float A[2][BM][LDA]; float B[2][BN][LDA]; } s;
        float Cs[BM][LDC];
    } sm;

    const int tid  = threadIdx.x;
    const int warp = tid >> 5;
    const int wm = warp / WARPS_N, wn = warp % WARPS_N;
    const int col0 = blockIdx.x * BN;
    const int row0 = blockIdx.y * BM;
    const int Kloc = K / KSPLIT;
    const int kbase = blockIdx.z * Kloc;
    float* Cout = C + (size_t)blockIdx.z * M * N;

    wmma::fragment<wmma::accumulator, 16, 16, 8, float> acc[TM][TN];
    #pragma unroll
    for (int i = 0; i < TM; i++)
        #pragma unroll
        for (int j = 0; j < TN; j++)
            wmma::fill_fragment(acc[i][j], 0.f);

    const int NIT = Kloc / BK;

    auto load_tile = [&](int it, int st) {
        const int k0 = kbase + it * BK;
        #pragma unroll
        for (int i = tid; i < BM * (BK / 4); i += 256) {
            int r = i / (BK / 4), c = (i % (BK / 4)) * 4;
            cp_async16(&sm.s.A[st][r][c], &A[(size_t)(row0 + r) * K + k0 + c]);
        }
        #pragma unroll
        for (int i = tid; i < BN * (BK / 4); i += 256) {
            int r = i / (BK / 4), c = (i % (BK / 4)) * 4;
            cp_async16(&sm.s.B[st][r][c], &W[(size_t)(col0 + r) * K + k0 + c]);
        }
    };

    load_tile(0, 0);
    cp_commit();

    for (int it = 0; it < NIT; it++) {
        if (it + 1 < NIT) load_tile(it + 1, (it + 1) & 1);
        cp_commit();
        cp_wait1();
        __syncthreads();

        const int st = it & 1;
        #pragma unroll
        for (int kk = 0; kk < BK; kk += 8) {
            wmma::fragment<wmma::matrix_a, 16, 16, 8, wmma::precision::tf32, wmma::row_major> fa[TM];
            wmma::fragment<wmma::matrix_b, 16, 16, 8, wmma::precision::tf32, wmma::col_major> fb[TN];
            #pragma unroll
            for (int i = 0; i < TM; i++)
                wmma::load_matrix_sync(fa[i], &sm.s.A[st][wm * WM + i * 16][kk], LDA);
            #pragma unroll
            for (int j = 0; j < TN; j++)
                wmma::load_matrix_sync(fb[j], &sm.s.B[st][wn * WN + j * 16][kk], LDA);
            #pragma unroll
            for (int i = 0; i < TM; i++)
                #pragma unroll
                for (int j = 0; j < TN; j++)
                    wmma::mma_sync(acc[i][j], fa[i], fb[j], acc[i][j]);
        }
        __syncthreads();
    }

    // epilogue via smem (aliased)
    #pragma unroll
    for (int i = 0; i < TM; i++)
        #pragma unroll
        for (int j = 0; j < TN; j++)
            wmma::store_matrix_sync(&sm.Cs[wm * WM + i * 16][wn * WN + j * 16],
                                    acc[i][j], LDC, wmma::mem_row_major);
    __syncthreads();

    #pragma unroll
    for (int i = tid; i < BM * (BN / 4); i += 256) {
        int r = i / (BN / 4), c = (i % (BN / 4)) * 4;
        float4 v = *(float4*)&sm.Cs[r][c];
        if (BIASRELU) {
            float4 b4 = *(const float4*)&bias[col0 + c];
            v.x = fmaxf(v.x + b4.x, 0.f);
            v.y = fmaxf(v.y + b4.y, 0.f);
            v.z = fmaxf(v.z + b4.z, 0.f);
            v.w = fmaxf(v.w + b4.w, 0.f);
        }
        *(float4*)&Cout[(size_t)(row0 + r) * N + col0 + c] = v;
    }
}

// ============================================================
// LayerNorm with fused NP-way split-K combine:
// v = sum_k parts[k] + res + bias[n]; out = LN(v)*g + be
// ============================================================
template <int NP>
__global__ __launch_bounds__(256) void ln_kernel(
    const float* __restrict__ parts,
    const float* __restrict__ bias, const float* __restrict__ res,
    const float* __restrict__ g, const float* __restrict__ be,
    float* __restrict__ out)
{
    const int row = blockIdx.x;
    const int tid = threadIdx.x;
    const size_t i0 = (size_t)row * D + tid;
    const size_t i1 = i0 + 256;
    float v0 = res[i0] + bias[tid];
    float v1 = res[i1] + bias[tid + 256];
    #pragma unroll
    for (int k = 0; k < NP; k++) {
        v0 += parts[(size_t)k * S * D + i0];
        v1 += parts[(size_t)k * S * D + i1];
    }

    __shared__ float red[8];
    __shared__ float mu_s, rstd_s;

    float s = v0 + v1;
    #pragma unroll
    for (int o = 16; o > 0; o >>= 1) s += __shfl_xor_sync(0xffffffffu, s, o);
    if ((tid & 31) == 0) red[tid >> 5] = s;
    __syncthreads();
    if (tid == 0) {
        float t = 0.f;
        #pragma unroll
        for (int i = 0; i < 8; i++) t += red[i];
        mu_s = t * (1.0f / D);
    }
    __syncthreads();
    const float mu = mu_s;
    const float d0 = v0 - mu, d1 = v1 - mu;
    float vs = d0 * d0 + d1 * d1;
    __syncthreads();
    #pragma unroll
    for (int o = 16; o > 0; o >>= 1) vs += __shfl_xor_sync(0xffffffffu, vs, o);
    if ((tid & 31) == 0) red[tid >> 5] = vs;
    __syncthreads();
    if (tid == 0) {
        float t = 0.f;
        #pragma unroll
        for (int i = 0; i < 8; i++) t += red[i];
        rstd_s = rsqrtf(t * (1.0f / D) + 1e-5f);
    }
    __syncthreads();
    const float rstd = rstd_s;
    out[i0] = d0 * rstd * g[tid] + be[tid];
    out[i1] = d1 * rstd * g[tid + 256] + be[tid + 256];
}

// ============================================================
extern "C" void kernel_launch(void* const* d_in, const int* in_sizes, int n_in,
                              void* d_out, int out_size)
{
    const float* tgt  = (const float*)d_in[0];
    const float* mem  = (const float*)d_in[1];
    const float* pos  = (const float*)d_in[2];
    const float* qpos = (const float*)d_in[3];
    const int*   aidx = (const int*)d_in[4];
    const float* Wt2  = (const float*)d_in[5];
    const float* bt2  = (const float*)d_in[6];
    const float* W1   = (const float*)d_in[7];
    const float* b1   = (const float*)d_in[8];
    const float* W2   = (const float*)d_in[9];
    const float* b2   = (const float*)d_in[10];
    const float* g2   = (const float*)d_in[11];
    const float* be2  = (const float*)d_in[12];
    const float* g3   = (const float*)d_in[13];
    const float* be3  = (const float*)d_in[14];
    float* out = (float*)d_out;

    float *rctx_p, *x_p, *h_p, *part_p;
    cudaGetSymbolAddress((void**)&rctx_p, g_rctx);
    cudaGetSymbolAddress((void**)&x_p,    g_x);
    cudaGetSymbolAddress((void**)&h_p,    g_h);
    cudaGetSymbolAddress((void**)&part_p, g_part);

    // 1) attention -> relu(ctx)
    attn_kernel<<<S / G, 512>>>(tgt, mem, pos, qpos, aidx);

    // 2) tgt2 partials = rctx @ Wt2^T   [512,512,K=512], splitK=2
    {
        dim3 grid(D / 128, S / 64, 2);
        gemm_tc<2, false><<<grid, 256>>>(rctx_p, Wt2, nullptr, part_p, S, D, D);
    }
    // 3) x = LN(tgt + p0 + p1 + bt2)
    ln_kernel<2><<<S, 256>>>(part_p, bt2, tgt, g2, be2, x_p);

    // 4) h = relu(x @ W1^T + b1)   [512,2048,K=512]
    {
        dim3 grid(DFF / 128, S / 64, 1);
        gemm_tc<1, true><<<grid, 256>>>(x_p, W1, b1, h_p, S, DFF, D);
    }
    // 5) ffn partials = h @ W2^T   [512,512,K=2048], splitK=4
    {
        dim3 grid(D / 128, S / 64, 4);
        gemm_tc<4, false><<<grid, 256>>>(h_p, W2, nullptr, part_p, S, D, DFF);
    }
    // 6) out = LN(x + p0..p3 + b2)
    ln_kernel<4><<<S, 256>>>(part_p, b2, x_p, g3, be3, out);
}

// round 8
// speedup vs baseline: 3.4671x; 1.7055x over previous
#include <cuda_runtime.h>
#include <cuda_fp16.h>
#include <cstdint>
#include <mma.h>
#include <math.h>

using namespace nvcuda;

#define S   512
#define T   16384
#define D   512
#define DFF 2048
#define SEG (T / S)          // 32 frames per segment
#define G   4                // queries per attention block

// -------- scratch (allocation-free: __device__ globals) --------
__device__ __half g_rctx_h[S * D];            // relu(ctx) fp16
__device__ __half g_xh[S * D];                // x fp16 (GEMM A)
__device__ __half g_h[S * DFF];               // relu FFN hidden fp16
__device__ __half g_wh[D * D + DFF * D + D * DFF];  // fp16 weights
__device__ float  g_x[S * D];                 // x fp32 (residual)
__device__ float  g_part[4 * S * D];          // split-K partials

// ============================================================
// cp.async helpers
// ============================================================
__device__ __forceinline__ void cp_async16(void* sm, const void* gm) {
    unsigned int a = (unsigned int)__cvta_generic_to_shared(sm);
    asm volatile("cp.async.cg.shared.global [%0], [%1], 16;" :: "r"(a), "l"(gm) : "memory");
}
__device__ __forceinline__ void cp_commit() {
    asm volatile("cp.async.commit_group;" ::: "memory");
}
__device__ __forceinline__ void cp_wait1() {
    asm volatile("cp.async.wait_group 1;" ::: "memory");
}

// ============================================================
// Weight conversion fp32 -> fp16 (once per launch, 3 matrices)
// blockIdx.y selects matrix.
// ============================================================
__global__ __launch_bounds__(256) void cvt_kernel(
    const float* __restrict__ w0, const float* __restrict__ w1,
    const float* __restrict__ w2)
{
    const int mat = blockIdx.y;
    const float2* src;
    __half2* dst;
    int n2;
    if (mat == 0) { src = (const float2*)w0; dst = (__half2*)g_wh;                 n2 = D * D / 2; }
    else if (mat == 1) { src = (const float2*)w1; dst = (__half2*)(g_wh + D * D);  n2 = DFF * D / 2; }
    else { src = (const float2*)w2; dst = (__half2*)(g_wh + D * D + DFF * D);      n2 = D * DFF / 2; }
    for (int i = blockIdx.x * 256 + threadIdx.x; i < n2; i += gridDim.x * 256)
        dst[i] = __float22half2_rn(src[i]);
}

// ============================================================
// Kernel 1: banded attention -> relu(ctx) fp16. G=4 queries/block.
// ============================================================
__global__ __launch_bounds__(512) void attn_kernel(
    const float* __restrict__ tgt, const float* __restrict__ mem,
    const float* __restrict__ pos, const float* __restrict__ qpos,
    const int*   __restrict__ aidx)
{
    const int blk  = blockIdx.x;
    const int tid  = threadIdx.x;
    const int warp = tid >> 5, lane = tid & 31;
    const int q0   = blk * G;

    const int t0 = max(0, q0 - 1) * SEG;
    const int t1 = min(S, q0 + G + 1) * SEG;
    const int nf = t1 - t0;                      // 160 or 192

    __shared__ float4 qs[G][D / 4];
    __shared__ float  sp[G][(G + 2) * SEG];
    __shared__ float  invd[G];

    for (int i = tid; i < G * (D / 4); i += 512) {
        int qi = i / (D / 4), d4 = i % (D / 4);
        float4 tv = ((const float4*)tgt)[(size_t)(q0 + qi) * (D / 4) + d4];
        float4 pv = ((const float4*)qpos)[(size_t)(q0 + qi) * (D / 4) + d4];
        qs[qi][d4] = make_float4(tv.x + pv.x, tv.y + pv.y, tv.z + pv.z, tv.w + pv.w);
    }
    __syncthreads();

    const float scale = 0.04419417382415922f;  // 1/sqrt(512)

    for (int base = warp; base < nf; base += 32) {
        const int fA = base;
        const int fB = base + 16;
        const bool hasB = fB < nf;
        const int tA = t0 + fA;
        const int tB = t0 + (hasB ? fB : fA);
        const float4* mA = (const float4*)mem + (size_t)tA * (D / 4);
        const float4* pA = (const float4*)pos + (size_t)tA * (D / 4);
        const float4* mB = (const float4*)mem + (size_t)tB * (D / 4);
        const float4* pB = (const float4*)pos + (size_t)tB * (D / 4);

        float aA0 = 0.f, aA1 = 0.f, aA2 = 0.f, aA3 = 0.f;
        float aB0 = 0.f, aB1 = 0.f, aB2 = 0.f, aB3 = 0.f;
        #pragma unroll
        for (int i = 0; i < 4; i++) {
            const int d4 = lane + 32 * i;
            float4 ma = mA[d4], pa = pA[d4];
            float4 mb = mB[d4], pb = pB[d4];
            float4 kA = make_float4(ma.x + pa.x, ma.y + pa.y, ma.z + pa.z, ma.w + pa.w);
            float4 kB = make_float4(mb.x + pb.x, mb.y + pb.y, mb.z + pb.z, mb.w + pb.w);
            float4 qa = qs[0][d4], qb = qs[1][d4], qc = qs[2][d4], qd = qs[3][d4];
            aA0 = fmaf(kA.x, qa.x, fmaf(kA.y, qa.y, fmaf(kA.z, qa.z, fmaf(kA.w, qa.w, aA0))));
            aA1 = fmaf(kA.x, qb.x, fmaf(kA.y, qb.y, fmaf(kA.z, qb.z, fmaf(kA.w, qb.w, aA1))));
            aA2 = fmaf(kA.x, qc.x, fmaf(kA.y, qc.y, fmaf(kA.z, qc.z, fmaf(kA.w, qc.w, aA2))));
            aA3 = fmaf(kA.x, qd.x, fmaf(kA.y, qd.y, fmaf(kA.z, qd.z, fmaf(kA.w, qd.w, aA3))));
            aB0 = fmaf(kB.x, qa.x, fmaf(kB.y, qa.y, fmaf(kB.z, qa.z, fmaf(kB.w, qa.w, aB0))));
            aB1 = fmaf(kB.x, qb.x, fmaf(kB.y, qb.y, fmaf(kB.z, qb.z, fmaf(kB.w, qb.w, aB1))));
            aB2 = fmaf(kB.x, qc.x, fmaf(kB.y, qc.y, fmaf(kB.z, qc.z, fmaf(kB.w, qc.w, aB2))));
            aB3 = fmaf(kB.x, qd.x, fmaf(kB.y, qd.y, fmaf(kB.z, qd.z, fmaf(kB.w, qd.w, aB3))));
        }
        #pragma unroll
        for (int o = 16; o > 0; o >>= 1) {
            aA0 += __shfl_xor_sync(0xffffffffu, aA0, o);
            aA1 += __shfl_xor_sync(0xffffffffu, aA1, o);
            aA2 += __shfl_xor_sync(0xffffffffu, aA2, o);
            aA3 += __shfl_xor_sync(0xffffffffu, aA3, o);
            aB0 += __shfl_xor_sync(0xffffffffu, aB0, o);
            aB1 += __shfl_xor_sync(0xffffffffu, aB1, o);
            aB2 += __shfl_xor_sync(0xffffffffu, aB2, o);
            aB3 += __shfl_xor_sync(0xffffffffu, aB3, o);
        }
        if (lane == 0) {
            {
                const int a = aidx[tA];
                int d0 = a - q0;     if (d0 < 0) d0 = -d0;
                int d1 = a - q0 - 1; if (d1 < 0) d1 = -d1;
                int d2 = a - q0 - 2; if (d2 < 0) d2 = -d2;
                int d3 = a - q0 - 3; if (d3 < 0) d3 = -d3;
                sp[0][fA] = (d0 <= 1) ? aA0 * scale : -INFINITY;
                sp[1][fA] = (d1 <= 1) ? aA1 * scale : -INFINITY;
                sp[2][fA] = (d2 <= 1) ? aA2 * scale : -INFINITY;
                sp[3][fA] = (d3 <= 1) ? aA3 * scale : -INFINITY;
            }
            if (hasB) {
                const int a = aidx[tB];
                int d0 = a - q0;     if (d0 < 0) d0 = -d0;
                int d1 = a - q0 - 1; if (d1 < 0) d1 = -d1;
                int d2 = a - q0 - 2; if (d2 < 0) d2 = -d2;
                int d3 = a - q0 - 3; if (d3 < 0) d3 = -d3;
                sp[0][fB] = (d0 <= 1) ? aB0 * scale : -INFINITY;
                sp[1][fB] = (d1 <= 1) ? aB1 * scale : -INFINITY;
                sp[2][fB] = (d2 <= 1) ? aB2 * scale : -INFINITY;
                sp[3][fB] = (d3 <= 1) ? aB3 * scale : -INFINITY;
            }
        }
    }
    __syncthreads();

    if (warp < G) {
        const int qi = warp;
        float m = -INFINITY;
        for (int f = lane; f < nf; f += 32) m = fmaxf(m, sp[qi][f]);
        #pragma unroll
        for (int o = 16; o > 0; o >>= 1)
            m = fmaxf(m, __shfl_xor_sync(0xffffffffu, m, o));
        float ssum = 0.f;
        for (int f = lane; f < nf; f += 32) {
            float e = __expf(sp[qi][f] - m);
            sp[qi][f] = e;
            ssum += e;
        }
        #pragma unroll
        for (int o = 16; o > 0; o >>= 1)
            ssum += __shfl_xor_sync(0xffffffffu, ssum, o);
        if (lane == 0) invd[qi] = 1.f / ssum;
    }
    __syncthreads();

    // ctx -> relu -> fp16
    {
        const int qi = tid >> 7;
        const int dc = tid & 127;
        const int s  = q0 + qi;
        const int fb = max(0, s - 1) * SEG - t0;
        const int fe = min(S, s + 2) * SEG - t0;
        const float4* m4 = (const float4*)mem;
        float4 acc = make_float4(0.f, 0.f, 0.f, 0.f);
        #pragma unroll 4
        for (int f = fb; f < fe; f++) {
            const float p = sp[qi][f];
            float4 mv = m4[(size_t)(t0 + f) * (D / 4) + dc];
            acc.x = fmaf(p, mv.x, acc.x);
            acc.y = fmaf(p, mv.y, acc.y);
            acc.z = fmaf(p, mv.z, acc.z);
            acc.w = fmaf(p, mv.w, acc.w);
        }
        const float iv = invd[qi];
        acc.x = fmaxf(acc.x * iv, 0.f);
        acc.y = fmaxf(acc.y * iv, 0.f);
        acc.z = fmaxf(acc.z * iv, 0.f);
        acc.w = fmaxf(acc.w * iv, 0.f);
        __half2* outp = (__half2*)g_rctx_h + (size_t)s * (D / 2) + dc * 2;
        outp[0] = __floats2half2_rn(acc.x, acc.y);
        outp[1] = __floats2half2_rn(acc.z, acc.w);
    }
}

// ============================================================
// FP16 tensor-core GEMM, double-buffered cp.async.
// BM=BN=64, BK=64, 128 threads (4 warps, 32x32 warp tiles).
// MODE 0: fp32 raw partials to ((float*)C) + z*M*N
// MODE 1: relu(acc + bias) -> fp16 to (half*)C
// ============================================================
template <int KSPLIT, int MODE>
__global__ __launch_bounds__(128) void gemm_h(
    const __half* __restrict__ A, const __half* __restrict__ W,
    const float* __restrict__ bias, void* __restrict__ C,
    int M, int N, int K)
{
    constexpr int BM = 64, BN = 64, BK = 64;
    constexpr int LDA = BK + 8;    // halfs; row = 144B, 16B-aligned
    constexpr int LDC = BN + 4;    // floats

    __shared__ union SmemU {
        struct { __half A[2][BM][LDA]; __half B[2][BN][LDA]; } s;
        float Cs[BM][LDC];
    } sm;

    const int tid  = threadIdx.x;
    const int warp = tid >> 5;
    const int wm = warp >> 1, wn = warp & 1;
    const int col0 = blockIdx.x * BN;
    const int row0 = blockIdx.y * BM;
    const int Kloc = K / KSPLIT;
    const int kbase = blockIdx.z * Kloc;

    wmma::fragment<wmma::accumulator, 16, 16, 16, float> acc[2][2];
    #pragma unroll
    for (int i = 0; i < 2; i++)
        #pragma unroll
        for (int j = 0; j < 2; j++)
            wmma::fill_fragment(acc[i][j], 0.f);

    const int NIT = Kloc / BK;

    auto load_tile = [&](int it, int st) {
        const int k0 = kbase + it * BK;
        // per tile: 64 rows x 8 chunks(16B=8 halfs); 512 chunks; 4/thread
        #pragma unroll
        for (int i = tid; i < BM * (BK / 8); i += 128) {
            int r = i >> 3, c = (i & 7) * 8;
            cp_async16(&sm.s.A[st][r][c], &A[(size_t)(row0 + r) * K + k0 + c]);
        }
        #pragma unroll
        for (int i = tid; i < BN * (BK / 8); i += 128) {
            int r = i >> 3, c = (i & 7) * 8;
            cp_async16(&sm.s.B[st][r][c], &W[(size_t)(col0 + r) * K + k0 + c]);
        }
    };

    load_tile(0, 0);
    cp_commit();

    for (int it = 0; it < NIT; it++) {
        if (it + 1 < NIT) load_tile(it + 1, (it + 1) & 1);
        cp_commit();
        cp_wait1();
        __syncthreads();

        const int st = it & 1;
        #pragma unroll
        for (int kk = 0; kk < BK; kk += 16) {
            wmma::fragment<wmma::matrix_a, 16, 16, 16, __half, wmma::row_major> fa[2];
            wmma::fragment<wmma::matrix_b, 16, 16, 16, __half, wmma::col_major> fb[2];
            #pragma unroll
            for (int i = 0; i < 2; i++)
                wmma::load_matrix_sync(fa[i], &sm.s.A[st][wm * 32 + i * 16][kk], LDA);
            #pragma unroll
            for (int j = 0; j < 2; j++)
                wmma::load_matrix_sync(fb[j], &sm.s.B[st][wn * 32 + j * 16][kk], LDA);
            #pragma unroll
            for (int i = 0; i < 2; i++)
                #pragma unroll
                for (int j = 0; j < 2; j++)
                    wmma::mma_sync(acc[i][j], fa[i], fb[j], acc[i][j]);
        }
        __syncthreads();
    }

    // epilogue via smem (aliased over stage buffers)
    #pragma unroll
    for (int i = 0; i < 2; i++)
        #pragma unroll
        for (int j = 0; j < 2; j++)
            wmma::store_matrix_sync(&sm.Cs[wm * 32 + i * 16][wn * 32 + j * 16],
                                    acc[i][j], LDC, wmma::mem_row_major);
    __syncthreads();

    if (MODE == 0) {
        float* Co = (float*)C + (size_t)blockIdx.z * M * N;
        #pragma unroll
        for (int i = tid; i < BM * (BN / 4); i += 128) {
            int r = i / (BN / 4), c = (i % (BN / 4)) * 4;
            float4 v = *(float4*)&sm.Cs[r][c];
            *(float4*)&Co[(size_t)(row0 + r) * N + col0 + c] = v;
        }
    } else {
        __half* Co = (__half*)C;
        #pragma unroll
        for (int i = tid; i < BM * (BN / 4); i += 128) {
            int r = i / (BN / 4), c = (i % (BN / 4)) * 4;
            float4 v = *(float4*)&sm.Cs[r][c];
            float4 b4 = *(const float4*)&bias[col0 + c];
            v.x = fmaxf(v.x + b4.x, 0.f);
            v.y = fmaxf(v.y + b4.y, 0.f);
            v.z = fmaxf(v.z + b4.z, 0.f);
            v.w = fmaxf(v.w + b4.w, 0.f);
            __half2* o2 = (__half2*)&Co[(size_t)(row0 + r) * N + col0 + c];
            o2[0] = __floats2half2_rn(v.x, v.y);
            o2[1] = __floats2half2_rn(v.z, v.w);
        }
    }
}

// ============================================================
// LayerNorm with fused NP-way split-K combine.
// WH: also write fp16 copy (GEMM A operand) to g_xh.
// ============================================================
template <int NP, bool WH>
__global__ __launch_bounds__(256) void ln_kernel(
    const float* __restrict__ parts,
    const float* __restrict__ bias, const float* __restrict__ res,
    const float* __restrict__ g, const float* __restrict__ be,
    float* __restrict__ out)
{
    const int row = blockIdx.x;
    const int tid = threadIdx.x;
    const size_t i0 = (size_t)row * D + tid;
    const size_t i1 = i0 + 256;
    float v0 = res[i0] + bias[tid];
    float v1 = res[i1] + bias[tid + 256];
    #pragma unroll
    for (int k = 0; k < NP; k++) {
        v0 += parts[(size_t)k * S * D + i0];
        v1 += parts[(size_t)k * S * D + i1];
    }

    __shared__ float red[8];
    __shared__ float mu_s, rstd_s;

    float s = v0 + v1;
    #pragma unroll
    for (int o = 16; o > 0; o >>= 1) s += __shfl_xor_sync(0xffffffffu, s, o);
    if ((tid & 31) == 0) red[tid >> 5] = s;
    __syncthreads();
    if (tid == 0) {
        float t = 0.f;
        #pragma unroll
        for (int i = 0; i < 8; i++) t += red[i];
        mu_s = t * (1.0f / D);
    }
    __syncthreads();
    const float mu = mu_s;
    const float d0 = v0 - mu, d1 = v1 - mu;
    float vs = d0 * d0 + d1 * d1;
    __syncthreads();
    #pragma unroll
    for (int o = 16; o > 0; o >>= 1) vs += __shfl_xor_sync(0xffffffffu, vs, o);
    if ((tid & 31) == 0) red[tid >> 5] = vs;
    __syncthreads();
    if (tid == 0) {
        float t = 0.f;
        #pragma unroll
        for (int i = 0; i < 8; i++) t += red[i];
        rstd_s = rsqrtf(t * (1.0f / D) + 1e-5f);
    }
    __syncthreads();
    const float rstd = rstd_s;
    const float o0 = d0 * rstd * g[tid] + be[tid];
    const float o1 = d1 * rstd * g[tid + 256] + be[tid + 256];
    out[i0] = o0;
    out[i1] = o1;
    if (WH) {
        g_xh[i0] = __float2half_rn(o0);
        g_xh[i1] = __float2half_rn(o1);
    }
}

// ============================================================
extern "C" void kernel_launch(void* const* d_in, const int* in_sizes, int n_in,
                              void* d_out, int out_size)
{
    const float* tgt  = (const float*)d_in[0];
    const float* mem  = (const float*)d_in[1];
    const float* pos  = (const float*)d_in[2];
    const float* qpos = (const float*)d_in[3];
    const int*   aidx = (const int*)d_in[4];
    const float* Wt2  = (const float*)d_in[5];
    const float* bt2  = (const float*)d_in[6];
    const float* W1   = (const float*)d_in[7];
    const float* b1   = (const float*)d_in[8];
    const float* W2   = (const float*)d_in[9];
    const float* b2   = (const float*)d_in[10];
    const float* g2   = (const float*)d_in[11];
    const float* be2  = (const float*)d_in[12];
    const float* g3   = (const float*)d_in[13];
    const float* be3  = (const float*)d_in[14];
    float* out = (float*)d_out;

    __half *rctx_p, *xh_p, *h_p, *wh_p;
    float *x_p, *part_p;
    cudaGetSymbolAddress((void**)&rctx_p, g_rctx_h);
    cudaGetSymbolAddress((void**)&xh_p,   g_xh);
    cudaGetSymbolAddress((void**)&h_p,    g_h);
    cudaGetSymbolAddress((void**)&wh_p,   g_wh);
    cudaGetSymbolAddress((void**)&x_p,    g_x);
    cudaGetSymbolAddress((void**)&part_p, g_part);

    const __half* whT2 = wh_p;
    const __half* wh1  = wh_p + D * D;
    const __half* wh2  = wh_p + D * D + (size_t)DFF * D;

    // 0) weights fp32 -> fp16
    cvt_kernel<<<dim3(128, 3), 256>>>(Wt2, W1, W2);

    // 1) attention -> relu(ctx) fp16
    attn_kernel<<<S / G, 512>>>(tgt, mem, pos, qpos, aidx);

    // 2) tgt2 partials = rctx @ Wt2^T   [512,512,K=512], splitK=4
    gemm_h<4, 0><<<dim3(D / 64, S / 64, 4), 128>>>(rctx_p, whT2, nullptr, part_p, S, D, D);

    // 3) x = LN(tgt + sum parts + bt2); also write fp16 x
    ln_kernel<4, true><<<S, 256>>>(part_p, bt2, tgt, g2, be2, x_p);

    // 4) h = relu(x @ W1^T + b1) fp16   [512,2048,K=512]
    gemm_h<1, 1><<<dim3(DFF / 64, S / 64, 1), 128>>>(xh_p, wh1, b1, h_p, S, DFF, D);

    // 5) ffn partials = h @ W2^T   [512,512,K=2048], splitK=4
    gemm_h<4, 0><<<dim3(D / 64, S / 64, 4), 128>>>(h_p, wh2, nullptr, part_p, S, D, DFF);

    // 6) out = LN(x + sum parts + b2)
    ln_kernel<4, false><<<S, 256>>>(part_p, b2, x_p, g3, be3, out);
}